// round 16
// baseline (speedup 1.0000x reference)
#include <cuda_runtime.h>

#define NMAX 100000
#define EMAX 1600000
#define NG 64
#define NH 64

// ---- scratch (static device globals; no allocations allowed) ----
__device__ __align__(16) float g_h[(size_t)NMAX * NH];     // hs = h * dinv (pre-scaled)
__device__ __align__(16) float g_agg[(size_t)NMAX * NH];   // gemm-init'd: hs + bias*sqrt(deg)
__device__ float g_deg[NMAX];
__device__ float g_dinv[NMAX];
__device__ float g_rdeg[NMAX];           // sqrt(deg) = 1/dinv
__device__ __align__(8) int2 g_sd[EMAX]; // packed (src, dst)
__device__ float g_pooled[NG * NH];

// ---------------- degree prep ----------------

__global__ void k_init_deg(int n) {
    int i = blockIdx.x * blockDim.x + threadIdx.x;
    if (i < n) g_deg[i] = 1.0f;   // self-loop contributes 1
}

__global__ void k_prep_edges(const int* __restrict__ ei, int E, int n) {
    int e = blockIdx.x * blockDim.x + threadIdx.x;
    if (e < E) {
        int s = ei[e];
        int d = ei[(size_t)E + e];
        s = s < 0 ? 0 : (s >= n ? n - 1 : s);
        d = d < 0 ? 0 : (d >= n ? n - 1 : d);
        g_sd[e] = make_int2(s, d);
        atomicAdd(&g_deg[d], 1.0f);
    }
}

__global__ void k_dinv(int n) {
    int i = blockIdx.x * blockDim.x + threadIdx.x;
    if (i < n) {
        float deg = g_deg[i];
        float di  = rsqrtf(deg);
        g_dinv[i] = di;
        g_rdeg[i] = deg * di;      // sqrt(deg)
    }
}

// ---- GEMM: H = X @ W; epilogue writes hs = H*dinv and agg = hs + bias*sqrt(deg) ----
// SCALED_IN: X = dinv[row] * relu(g_agg[row]) (previous layer, in-place safe:
// each block reads exactly the rows it writes; __syncthreads separates).

template<int K, bool SCALED_IN>
__global__ void __launch_bounds__(256) k_gemm(const float* __restrict__ Xin,
                                              const float* __restrict__ W,
                                              const float* __restrict__ bias, int n) {
    __shared__ float Ws[64 * 64];
    __shared__ float Xs[64 * 68];

    const float* __restrict__ X = SCALED_IN ? (const float*)g_agg : Xin;
    const int tid  = threadIdx.x;
    const int row0 = blockIdx.x * 64;
    const int r = (tid >> 4) << 2;
    const int c = (tid & 15) << 2;

    float acc[4][4] = {};

    for (int kc = 0; kc < K; kc += 64) {
        for (int i = tid; i < 64 * 16; i += 256)
            ((float4*)Ws)[i] = ((const float4*)(W + (size_t)kc * 64))[i];
        for (int i = tid; i < 64 * 16; i += 256) {
            int rr = i >> 4, c4 = i & 15;
            float4 v = make_float4(0.f, 0.f, 0.f, 0.f);
            if (row0 + rr < n) {
                v = *((const float4*)(X + (size_t)(row0 + rr) * K + kc + c4 * 4));
                if (SCALED_IN) {
                    float di = g_dinv[row0 + rr];
                    v.x = fmaxf(v.x, 0.f) * di; v.y = fmaxf(v.y, 0.f) * di;
                    v.z = fmaxf(v.z, 0.f) * di; v.w = fmaxf(v.w, 0.f) * di;
                }
            }
            *((float4*)(Xs + rr * 68 + c4 * 4)) = v;
        }
        __syncthreads();

        #pragma unroll 16
        for (int k = 0; k < 64; k++) {
            float4 wb = *((const float4*)(Ws + k * 64 + c));
            float a0 = Xs[(r + 0) * 68 + k];
            float a1 = Xs[(r + 1) * 68 + k];
            float a2 = Xs[(r + 2) * 68 + k];
            float a3 = Xs[(r + 3) * 68 + k];
            acc[0][0] += a0 * wb.x; acc[0][1] += a0 * wb.y; acc[0][2] += a0 * wb.z; acc[0][3] += a0 * wb.w;
            acc[1][0] += a1 * wb.x; acc[1][1] += a1 * wb.y; acc[1][2] += a1 * wb.z; acc[1][3] += a1 * wb.w;
            acc[2][0] += a2 * wb.x; acc[2][1] += a2 * wb.y; acc[2][2] += a2 * wb.z; acc[2][3] += a2 * wb.w;
            acc[3][0] += a3 * wb.x; acc[3][1] += a3 * wb.y; acc[3][2] += a3 * wb.z; acc[3][3] += a3 * wb.w;
        }
        __syncthreads();
    }

    float bc0 = bias[c + 0], bc1 = bias[c + 1], bc2 = bias[c + 2], bc3 = bias[c + 3];

    #pragma unroll
    for (int i = 0; i < 4; i++) {
        int rr = row0 + r + i;
        if (rr < n) {
            float di = g_dinv[rr];
            float rd = g_rdeg[rr];
            // hs = h * dinv
            float4 h4 = make_float4(acc[i][0] * di, acc[i][1] * di,
                                    acc[i][2] * di, acc[i][3] * di);
            *((float4*)(g_h + (size_t)rr * 64 + c)) = h4;
            // agg init = hs + bias*sqrt(deg)   (so dinv*agg = h*dinv^2 + bias)
            float4 a4;
            a4.x = fmaf(bc0, rd, h4.x); a4.y = fmaf(bc1, rd, h4.y);
            a4.z = fmaf(bc2, rd, h4.z); a4.w = fmaf(bc3, rd, h4.w);
            *((float4*)(g_agg + (size_t)rr * 64 + c)) = a4;
        }
    }
}

// ---- edge scatter: agg[dst] += hs[src]  (norm factored out) ----
// 16 lanes per edge, one float4 per lane, 16B vector red.global.

__global__ void __launch_bounds__(256) k_scatter(int E) {
    int gid = blockIdx.x * blockDim.x + threadIdx.x;
    int e = gid >> 4;
    if (e >= E) return;
    int l = gid & 15;
    int2 sd = g_sd[e];
    float4 v = *((const float4*)(g_h + (size_t)sd.x * 64 + l * 4));
    float* p = g_agg + (size_t)sd.y * 64 + l * 4;
    asm volatile("red.global.add.v4.f32 [%0], {%1, %2, %3, %4};"
                 :: "l"(p), "f"(v.x), "f"(v.y), "f"(v.z), "f"(v.w)
                 : "memory");
}

// ---------------- mean-pool per graph (reads dinv*relu(g_agg); batch sorted) ----------------

__device__ __forceinline__ int lower_bound_i(const int* b, int n, int v) {
    int lo = 0, hi = n;
    while (lo < hi) {
        int m = (lo + hi) >> 1;
        if (b[m] < v) lo = m + 1; else hi = m;
    }
    return lo;
}

__global__ void k_pool(const int* __restrict__ batch, int n) {
    __shared__ int s_bounds[2];
    __shared__ float red[256];
    int g = blockIdx.x;
    if (threadIdx.x == 0) {
        s_bounds[0] = lower_bound_i(batch, n, g);
        s_bounds[1] = lower_bound_i(batch, n, g + 1);
    }
    __syncthreads();
    int start = s_bounds[0], end = s_bounds[1];
    int f = threadIdx.x & 63, j = threadIdx.x >> 6;
    float acc = 0.f;
    for (int node = start + j; node < end; node += 4)
        acc += fmaxf(g_agg[(size_t)node * 64 + f], 0.f) * g_dinv[node];
    red[threadIdx.x] = acc;
    __syncthreads();
    if (j == 0) {
        float s = red[f] + red[64 + f] + red[128 + f] + red[192 + f];
        float cnt = (float)(end - start);
        g_pooled[g * 64 + f] = s / fmaxf(cnt, 1.0f);
    }
}

// ---------------- final linear + softmax ----------------

__global__ void k_final(const float* __restrict__ Wl, const float* __restrict__ bl,
                        float* __restrict__ out) {
    int g = threadIdx.x;
    if (g >= NG) return;
    float p[64];
    #pragma unroll
    for (int f = 0; f < 64; f++) p[f] = g_pooled[g * 64 + f];
    float logits[10];
    #pragma unroll
    for (int c = 0; c < 10; c++) {
        float s = bl[c];
        #pragma unroll
        for (int f = 0; f < 64; f++) s += p[f] * Wl[f * 10 + c];
        logits[c] = s;
    }
    float m = logits[0];
    #pragma unroll
    for (int c = 1; c < 10; c++) m = fmaxf(m, logits[c]);
    float sum = 0.f;
    #pragma unroll
    for (int c = 0; c < 10; c++) { logits[c] = expf(logits[c] - m); sum += logits[c]; }
    float inv = 1.0f / sum;
    #pragma unroll
    for (int c = 0; c < 10; c++) out[g * 10 + c] = logits[c] * inv;
}

// ---------------- launch ----------------
// Inputs bound BY ELEMENT COUNT. edge_index/batch are int32 (JAX x64-disabled).

extern "C" void kernel_launch(void* const* d_in, const int* in_sizes, int n_in,
                              void* d_out, int out_size) {
    (void)out_size;
    const float* x = nullptr;
    const int* ei = nullptr;
    const int* batch = nullptr;
    const float *W1 = nullptr, *W2 = nullptr, *W3 = nullptr, *Wl = nullptr;
    const float *b1 = nullptr, *b2 = nullptr, *b3 = nullptr, *bl = nullptr;
    int ei_elems = 0, batch_elems = 0;
    int n4096 = 0, n64 = 0;

    for (int i = 0; i < n_in; i++) {
        int sz = in_sizes[i];
        const void* p = d_in[i];
        if (sz == 100000 * 128)      x = (const float*)p;
        else if (sz == 2 * 1600000)  { ei = (const int*)p; ei_elems = sz; }
        else if (sz == 100000)       { batch = (const int*)p; batch_elems = sz; }
        else if (sz == 128 * 64)     W1 = (const float*)p;
        else if (sz == 64 * 64)      { if (n4096++ == 0) W2 = (const float*)p; else W3 = (const float*)p; }
        else if (sz == 64)           { if (n64 == 0) b1 = (const float*)p;
                                       else if (n64 == 1) b2 = (const float*)p;
                                       else b3 = (const float*)p; n64++; }
        else if (sz == 64 * 10)      Wl = (const float*)p;
        else if (sz == 10)           bl = (const float*)p;
    }
    if (!x || !ei || !batch || !W1 || !W2 || !W3 || !b1 || !b2 || !b3 || !Wl || !bl)
        return;

    int n = batch_elems;     if (n > NMAX) n = NMAX;
    int E = ei_elems / 2;    if (E > EMAX) E = EMAX;

    const int TB = 256;
    const int nbN  = (n + TB - 1) / TB;
    const int nbE  = (E + TB - 1) / TB;
    const int nbGm = (n + 63) / 64;
    const int nbSc = (int)(((size_t)E * 16 + TB - 1) / TB);

    // prep: degree (with self-loop), dinv/rdeg, packed edges
    k_init_deg<<<nbN, TB>>>(n);
    k_prep_edges<<<nbE, TB>>>(ei, E, n);
    k_dinv<<<nbN, TB>>>(n);

    // layer 1 (K=128, input = x); gemm epilogue writes hs and agg-init
    k_gemm<128, false><<<nbGm, TB>>>(x, W1, b1, n);
    k_scatter<<<nbSc, TB>>>(E);

    // layer 2 (reads dinv*relu(g_agg) in-place)
    k_gemm<64, true><<<nbGm, TB>>>(nullptr, W2, b2, n);
    k_scatter<<<nbSc, TB>>>(E);

    // layer 3
    k_gemm<64, true><<<nbGm, TB>>>(nullptr, W3, b3, n);
    k_scatter<<<nbSc, TB>>>(E);

    // pool + classify
    k_pool<<<NG, TB>>>(batch, n);
    k_final<<<1, 64>>>(Wl, bl, (float*)d_out);
}